// round 2
// baseline (speedup 1.0000x reference)
#include <cuda_runtime.h>

#define RADIUS 5
#define KS 11
#define IMG_H 256
#define IMG_W 256
#define HW (IMG_H * IMG_W)
#define BX 32
#define BY 8
#define TX (BX + 2 * RADIUS)   // 42
#define TY (BY + 2 * RADIUS)   // 18
#define PLANE (TY * TX)        // 756
#define NCH 17                 // 8 guidance + 3 est + 3 var + 3 img
#define SMEM_BYTES (NCH * PLANE * 4)

// ---------------------------------------------------------------------------
// f32 ndtri replicating jax.scipy.special.ndtri (cephes constants, Horner
// with separate mul/add so nvcc cannot contract into FMA — matches XLA).
// ---------------------------------------------------------------------------
template <int N>
__device__ __forceinline__ float polevl_f(float x, const float (&c)[N]) {
    float r = c[0];
#pragma unroll
    for (int i = 1; i < N; ++i) r = __fadd_rn(__fmul_rn(r, x), c[i]);
    return r;
}

__device__ float ndtri_f32(float p) {
    const float P0[5] = {-5.99633501014107895267e1f, 9.80010754185999661536e1f,
                         -5.66762857469070293439e1f, 1.39312609387279679503e1f,
                         -1.23916583867381258016e0f};
    const float Q0[9] = {1.0f, 1.95448858338141759834e0f, 4.67627912898881538453e0f,
                         8.63602421390890590575e1f, -2.25462687854119370527e2f,
                         2.00260212380060660359e2f, -8.20372256168538034246e1f,
                         1.59056225126211695515e1f, -1.18331621121330003142e0f};
    const float P1[9] = {4.05544892305962419923e0f, 3.15251094599893866154e1f,
                         5.71628192246421288162e1f, 4.40805073893200834700e1f,
                         1.46849561928858024014e1f, 2.18663306850790267539e0f,
                         -1.40256079171354495875e-1f, -3.50424626827848203418e-2f,
                         -8.57456785154685413611e-4f};
    const float Q1[9] = {1.0f, 1.57799883256466749731e1f, 4.53907635128879210584e1f,
                         4.13172038254672030440e1f, 1.50425385692907503408e1f,
                         2.50464946208309415979e0f, -1.42182922854787788574e-1f,
                         -3.80806407691578277194e-2f, -9.33259480895457427372e-4f};
    const float P2[9] = {3.23774891776946035970e0f, 6.91522889068984211695e0f,
                         3.93881025292474443415e0f, 1.33303460815807542389e0f,
                         2.01485389549179081538e-1f, 1.23716634817820021358e-2f,
                         3.01581553508235416007e-4f, 2.65806974686737550832e-6f,
                         6.23974539184983651783e-9f};
    const float Q2[9] = {1.0f, 6.02427039364742014255e0f, 3.67983563856160859403e0f,
                         1.37702099489081330271e0f, 2.16236993594496635890e-1f,
                         1.34204006088543189037e-2f, 3.28014464682127739104e-4f,
                         2.89247864745380683936e-6f, 6.79019408009981274425e-9f};
    const float one_m_expm2 = 0.86466471676338730811f;  // 1 - exp(-2)
    const float expm2 = 0.13533528323661269189f;        // exp(-2)

    float mcp = (p > one_m_expm2) ? __fadd_rn(1.0f, -p) : p;
    float san = (mcp <= 0.0f) ? 0.5f : mcp;
    float x;
    if (san > expm2) {
        float w = __fadd_rn(san, -0.5f);
        float ww = __fmul_rn(w, w);
        float r = __fdiv_rn(polevl_f(ww, P0), polevl_f(ww, Q0));
        x = __fadd_rn(w, __fmul_rn(__fmul_rn(w, ww), r));
        x = __fmul_rn(x, -2.50662827463100050242f);  // -sqrt(2*pi)
    } else {
        float z = __fsqrt_rn(__fmul_rn(-2.0f, logf(san)));
        float ft = __fadd_rn(z, -__fdiv_rn(logf(z), z));
        float iz = __fdiv_rn(1.0f, z);
        float num, den;
        if (z >= 8.0f) { num = polevl_f(iz, P2); den = polevl_f(iz, Q2); }
        else           { num = polevl_f(iz, P1); den = polevl_f(iz, Q1); }
        float st = __fdiv_rn(__fdiv_rn(num, den), z);
        x = __fadd_rn(ft, -st);
    }
    return (p > one_m_expm2) ? x : -x;
}

__device__ float compute_gamma(int spp) {
    float z = ndtri_f32(0.9975f);   // 1 - ALPHA/2 rounded to f32
    double df = (double)(2 * spp - 2);
    float z2 = __fmul_rn(z, z);
    float z3 = __fmul_rn(z, z2);
    float z4 = __fmul_rn(z2, z2);
    float z5 = __fmul_rn(z, z4);
    float z7 = __fmul_rn(z3, z4);
    float g1 = __fdiv_rn(__fadd_rn(z3, z), (float)(4.0 * df));
    float g2 = __fdiv_rn(
        __fadd_rn(__fadd_rn(__fmul_rn(5.0f, z5), __fmul_rn(16.0f, z3)), __fmul_rn(3.0f, z)),
        (float)(96.0 * df * df));
    float g3 = __fdiv_rn(
        __fadd_rn(__fadd_rn(__fadd_rn(__fmul_rn(3.0f, z7), __fmul_rn(19.0f, z5)),
                            __fmul_rn(17.0f, z3)),
                  -__fmul_rn(15.0f, z)),
        (float)(384.0 * df * df * df));
    return __fadd_rn(__fadd_rn(__fadd_rn(z, g1), g2), g3);
}

// ---------------------------------------------------------------------------
// Main denoiser kernel: one thread = one output pixel, 32x8 tile per block,
// 17-channel halo tile (18x42) staged in shared memory.
// ---------------------------------------------------------------------------
__global__ void __launch_bounds__(BX * BY)
denoise_kernel(const float* __restrict__ img, const float* __restrict__ gd,
               const float* __restrict__ est, const float* __restrict__ var,
               const int* __restrict__ spp_p, float* __restrict__ out) {
    extern __shared__ float sm[];
    float* SG = sm;                 // 8 planes
    float* SE = sm + 8 * PLANE;     // 3 planes
    float* SV = sm + 11 * PLANE;    // 3 planes
    float* SI = sm + 14 * PLANE;    // 3 planes
    __shared__ float s_gamma;

    const int tx = threadIdx.x, ty = threadIdx.y;
    const int tid = ty * BX + tx;
    const int gx0 = blockIdx.x * BX - RADIUS;
    const int gy0 = blockIdx.y * BY - RADIUS;

    // Stage the halo tile (zero pad outside the image).
    for (int i = tid; i < PLANE; i += BX * BY) {
        int ly = i / TX;
        int lx = i - ly * TX;
        int gy = gy0 + ly, gx = gx0 + lx;
        bool inb = ((unsigned)gy < IMG_H) && ((unsigned)gx < IMG_W);
        int g = gy * IMG_W + gx;
#pragma unroll
        for (int c = 0; c < 8; ++c) SG[c * PLANE + i] = inb ? gd[c * HW + g] : 0.0f;
#pragma unroll
        for (int c = 0; c < 3; ++c) {
            SE[c * PLANE + i] = inb ? est[c * HW + g] : 0.0f;
            SV[c * PLANE + i] = inb ? var[c * HW + g] : 0.0f;
            SI[c * PLANE + i] = inb ? img[c * HW + g] : 0.0f;
        }
    }
    if (tid == 0) s_gamma = compute_gamma(spp_p[0]);
    __syncthreads();
    const float gamma = s_gamma;

    const int ci = (ty + RADIUS) * TX + (tx + RADIUS);
    float gc[8];
#pragma unroll
    for (int c = 0; c < 8; ++c) gc[c] = SG[c * PLANE + ci];
    float ce[3], cv[3];
#pragma unroll
    for (int c = 0; c < 3; ++c) {
        ce[c] = SE[c * PLANE + ci];
        cv[c] = SV[c * PLANE + ci];
    }
    const float SIGW[8] = {0.1f, 0.1f, 50.0f, 50.0f, 50.0f, 10.0f, 10.0f, 10.0f};

    float sumw = 0.0f;
    float acc[3] = {0.0f, 0.0f, 0.0f};

#pragma unroll 1
    for (int dy = 0; dy < KS; ++dy) {
        const int rb = (ty + dy) * TX + tx;
#pragma unroll
        for (int dx = 0; dx < KS; ++dx) {
            const int ni = rb + dx;
            // Bilateral guidance weight (two independent FMA chains).
            float s0 = 0.0f, s1 = 0.0f;
#pragma unroll
            for (int c = 0; c < 8; c += 2) {
                float d0 = SG[c * PLANE + ni] - gc[c];
                float d1 = SG[(c + 1) * PLANE + ni] - gc[c + 1];
                s0 = fmaf(d0 * d0, SIGW[c], s0);
                s1 = fmaf(d1 * d1, SIGW[c + 1], s1);
            }
            float bw = __expf(-0.5f * (s0 + s1));
            // Membership test (exact reference formula, IEEE ops).
            bool mem = true;
#pragma unroll
            for (int c = 0; c < 3; ++c) {
                float se = SE[c * PLANE + ni];
                float sv = SV[c * PLANE + ni];
                float d = ce[c] - se;
                float d2 = d * d;
                float num = 2.0f * d2 + cv[c] + sv;          // ((2*d2)+cv)+sv
                float den = 2.0f * ((d2 + cv[c]) + sv);
                float w = (den == 0.0f) ? 0.5f : __fdiv_rn(num, den);
                if (((cv[c] == 0.0f) | (sv == 0.0f)) & (ce[c] != se)) w = 1.0f;
                // w==1 -> 1/0 = inf -> t = inf -> compare false (matches ref).
                float t = __fsqrt_rn(__fdiv_rn(1.0f, 2.0f * (1.0f - w)) - 1.0f);
                mem = mem & (t < gamma);
            }
            if (dy == RADIUS && dx == RADIUS) mem = true;  // center forced in
            float fw = mem ? bw : 0.0f;
            sumw += fw;
#pragma unroll
            for (int c = 0; c < 3; ++c) acc[c] = fmaf(SI[c * PLANE + ni], fw, acc[c]);
        }
    }

    float inv = __fdiv_rn(1.0f, fmaxf(sumw, 1e-10f));
    const int ox = blockIdx.x * BX + tx;
    const int oy = blockIdx.y * BY + ty;
    const int o = oy * IMG_W + ox;
#pragma unroll
    for (int c = 0; c < 3; ++c) out[c * HW + o] = acc[c] * inv;
}

extern "C" void kernel_launch(void* const* d_in, const int* in_sizes, int n_in,
                              void* d_out, int out_size) {
    const float* img = (const float*)d_in[0];
    const float* gd  = (const float*)d_in[1];
    const float* est = (const float*)d_in[2];
    const float* var = (const float*)d_in[3];
    const int*   spp = (const int*)d_in[4];
    float* out = (float*)d_out;

    static bool attr_set = false;
    if (!attr_set) {
        cudaFuncSetAttribute(denoise_kernel,
                             cudaFuncAttributeMaxDynamicSharedMemorySize, SMEM_BYTES);
        attr_set = true;
    }
    dim3 block(BX, BY);
    dim3 grid(IMG_W / BX, IMG_H / BY);
    denoise_kernel<<<grid, block, SMEM_BYTES>>>(img, gd, est, var, spp, out);
}

// round 3
// speedup vs baseline: 4.5114x; 4.5114x over previous
#include <cuda_runtime.h>

#define RADIUS 5
#define KS 11
#define IMG_H 256
#define IMG_W 256
#define HW (IMG_H * IMG_W)
#define BX 32
#define BY 4
#define TX (BX + 2 * RADIUS)   // 42
#define TY (BY + 2 * RADIUS)   // 14
#define PLANE (TY * TX)        // 588

// Per-pixel packed smem: 2x float4 guidance (pre-scaled), float4 (e0,v0,e1,v1),
// float4 (e2,v2,i0,i1), float2 (i2,pad)  -> 72 B/px
#define SMEM_BYTES (PLANE * 72)

// ---------------------------------------------------------------------------
// f32 ndtri replicating jax.scipy.special.ndtri (cephes constants, Horner
// with separate mul/add so nvcc cannot contract into FMA — matches XLA).
// ---------------------------------------------------------------------------
template <int N>
__device__ __forceinline__ float polevl_f(float x, const float (&c)[N]) {
    float r = c[0];
#pragma unroll
    for (int i = 1; i < N; ++i) r = __fadd_rn(__fmul_rn(r, x), c[i]);
    return r;
}

__device__ float ndtri_f32(float p) {
    const float P0[5] = {-5.99633501014107895267e1f, 9.80010754185999661536e1f,
                         -5.66762857469070293439e1f, 1.39312609387279679503e1f,
                         -1.23916583867381258016e0f};
    const float Q0[9] = {1.0f, 1.95448858338141759834e0f, 4.67627912898881538453e0f,
                         8.63602421390890590575e1f, -2.25462687854119370527e2f,
                         2.00260212380060660359e2f, -8.20372256168538034246e1f,
                         1.59056225126211695515e1f, -1.18331621121330003142e0f};
    const float P1[9] = {4.05544892305962419923e0f, 3.15251094599893866154e1f,
                         5.71628192246421288162e1f, 4.40805073893200834700e1f,
                         1.46849561928858024014e1f, 2.18663306850790267539e0f,
                         -1.40256079171354495875e-1f, -3.50424626827848203418e-2f,
                         -8.57456785154685413611e-4f};
    const float Q1[9] = {1.0f, 1.57799883256466749731e1f, 4.53907635128879210584e1f,
                         4.13172038254672030440e1f, 1.50425385692907503408e1f,
                         2.50464946208309415979e0f, -1.42182922854787788574e-1f,
                         -3.80806407691578277194e-2f, -9.33259480895457427372e-4f};
    const float P2[9] = {3.23774891776946035970e0f, 6.91522889068984211695e0f,
                         3.93881025292474443415e0f, 1.33303460815807542389e0f,
                         2.01485389549179081538e-1f, 1.23716634817820021358e-2f,
                         3.01581553508235416007e-4f, 2.65806974686737550832e-6f,
                         6.23974539184983651783e-9f};
    const float Q2[9] = {1.0f, 6.02427039364742014255e0f, 3.67983563856160859403e0f,
                         1.37702099489081330271e0f, 2.16236993594496635890e-1f,
                         1.34204006088543189037e-2f, 3.28014464682127739104e-4f,
                         2.89247864745380683936e-6f, 6.79019408009981274425e-9f};
    const float one_m_expm2 = 0.86466471676338730811f;
    const float expm2 = 0.13533528323661269189f;

    float mcp = (p > one_m_expm2) ? __fadd_rn(1.0f, -p) : p;
    float san = (mcp <= 0.0f) ? 0.5f : mcp;
    float x;
    if (san > expm2) {
        float w = __fadd_rn(san, -0.5f);
        float ww = __fmul_rn(w, w);
        float r = __fdiv_rn(polevl_f(ww, P0), polevl_f(ww, Q0));
        x = __fadd_rn(w, __fmul_rn(__fmul_rn(w, ww), r));
        x = __fmul_rn(x, -2.50662827463100050242f);
    } else {
        float z = __fsqrt_rn(__fmul_rn(-2.0f, logf(san)));
        float ft = __fadd_rn(z, -__fdiv_rn(logf(z), z));
        float iz = __fdiv_rn(1.0f, z);
        float num, den;
        if (z >= 8.0f) { num = polevl_f(iz, P2); den = polevl_f(iz, Q2); }
        else           { num = polevl_f(iz, P1); den = polevl_f(iz, Q1); }
        float st = __fdiv_rn(__fdiv_rn(num, den), z);
        x = __fadd_rn(ft, -st);
    }
    return (p > one_m_expm2) ? x : -x;
}

__device__ float compute_gamma(int spp) {
    float z = ndtri_f32(0.9975f);
    double df = (double)(2 * spp - 2);
    float z2 = __fmul_rn(z, z);
    float z3 = __fmul_rn(z, z2);
    float z4 = __fmul_rn(z2, z2);
    float z5 = __fmul_rn(z, z4);
    float z7 = __fmul_rn(z3, z4);
    float g1 = __fdiv_rn(__fadd_rn(z3, z), (float)(4.0 * df));
    float g2 = __fdiv_rn(
        __fadd_rn(__fadd_rn(__fmul_rn(5.0f, z5), __fmul_rn(16.0f, z3)), __fmul_rn(3.0f, z)),
        (float)(96.0 * df * df));
    float g3 = __fdiv_rn(
        __fadd_rn(__fadd_rn(__fadd_rn(__fmul_rn(3.0f, z7), __fmul_rn(19.0f, z5)),
                            __fmul_rn(17.0f, z3)),
                  -__fmul_rn(15.0f, z)),
        (float)(384.0 * df * df * df));
    return __fadd_rn(__fadd_rn(__fadd_rn(z, g1), g2), g3);
}

// ---------------------------------------------------------------------------
// Denoiser: 32x4 output tile per block, 14x42 halo, packed float4 smem.
// Membership test collapsed to d^2 < gamma^2 * (cv+sv)  (exact algebra of the
// reference's w/t chain; see derivation: t^2 = d^2/(cv+sv)).
// ---------------------------------------------------------------------------
__global__ void __launch_bounds__(BX * BY)
denoise_kernel(const float* __restrict__ img, const float* __restrict__ gd,
               const float* __restrict__ est, const float* __restrict__ var,
               const int* __restrict__ spp_p, float* __restrict__ out) {
    extern __shared__ char smraw[];
    float4* G0 = (float4*)smraw;                          // g0..g3 (pre-scaled)
    float4* G1 = (float4*)(smraw + 16 * PLANE);           // g4..g7 (pre-scaled)
    float4* P1 = (float4*)(smraw + 32 * PLANE);           // e0,v0,e1,v1
    float4* P2 = (float4*)(smraw + 48 * PLANE);           // e2,v2,i0,i1
    float2* P3 = (float2*)(smraw + 64 * PLANE);           // i2,pad
    __shared__ float s_g2;

    const int tx = threadIdx.x, ty = threadIdx.y;
    const int tid = ty * BX + tx;
    const int gx0 = blockIdx.x * BX - RADIUS;
    const int gy0 = blockIdx.y * BY - RADIUS;

    // sqrt(0.5 * sigma_c): folds the bilateral sigma and the -0.5 into the data.
    const float SC0 = 0.223606797749979f;   // sqrt(0.05)
    const float SC2 = 5.0f;                 // sqrt(25)
    const float SC5 = 2.2360679774997896f;  // sqrt(5)

    for (int i = tid; i < PLANE; i += BX * BY) {
        int ly = i / TX;
        int lx = i - ly * TX;
        int gy = gy0 + ly, gx = gx0 + lx;
        bool inb = ((unsigned)gy < IMG_H) && ((unsigned)gx < IMG_W);
        int g = gy * IMG_W + gx;
        float4 a, b, p1, p2;
        float2 p3;
        if (inb) {
            a = make_float4(gd[g] * SC0, gd[HW + g] * SC0,
                            gd[2 * HW + g] * SC2, gd[3 * HW + g] * SC2);
            b = make_float4(gd[4 * HW + g] * SC2, gd[5 * HW + g] * SC5,
                            gd[6 * HW + g] * SC5, gd[7 * HW + g] * SC5);
            p1 = make_float4(est[g], var[g], est[HW + g], var[HW + g]);
            p2 = make_float4(est[2 * HW + g], var[2 * HW + g], img[g], img[HW + g]);
            p3 = make_float2(img[2 * HW + g], 0.0f);
        } else {
            a = make_float4(0.f, 0.f, 0.f, 0.f);
            b = a;
            p1 = a;
            p2 = a;
            p3 = make_float2(0.f, 0.f);
        }
        G0[i] = a; G1[i] = b; P1[i] = p1; P2[i] = p2; P3[i] = p3;
    }
    if (tid == 0) {
        float gm = compute_gamma(spp_p[0]);
        s_g2 = gm * gm;
    }
    __syncthreads();
    const float g2 = s_g2;

    const int ci = (ty + RADIUS) * TX + (tx + RADIUS);
    const float4 cg0 = G0[ci], cg1 = G1[ci];
    const float4 cp1 = P1[ci], cp2 = P2[ci];
    const float ce0 = cp1.x, cv0 = cp1.y, ce1 = cp1.z, cv1 = cp1.w;
    const float ce2 = cp2.x, cv2 = cp2.y;
    const bool cz0 = (cv0 == 0.0f), cz1 = (cv1 == 0.0f), cz2 = (cv2 == 0.0f);

    float sumw = 0.0f;
    float ac0 = 0.0f, ac1 = 0.0f, ac2 = 0.0f;

#pragma unroll 1
    for (int dy = 0; dy < KS; ++dy) {
        const int rb = (ty + dy) * TX + tx;
#pragma unroll
        for (int dx = 0; dx < KS; ++dx) {
            const int ni = rb + dx;
            const float4 a = G0[ni], b = G1[ni];
            // Bilateral weight: sigma and 0.5 pre-folded into staged guidance.
            float da0 = a.x - cg0.x, da1 = a.y - cg0.y;
            float da2 = a.z - cg0.z, da3 = a.w - cg0.w;
            float db0 = b.x - cg1.x, db1 = b.y - cg1.y;
            float db2 = b.z - cg1.z, db3 = b.w - cg1.w;
            float s0 = da0 * da0;
            float s1 = db0 * db0;
            s0 = fmaf(da1, da1, s0); s1 = fmaf(db1, db1, s1);
            s0 = fmaf(da2, da2, s0); s1 = fmaf(db2, db2, s1);
            s0 = fmaf(da3, da3, s0); s1 = fmaf(db3, db3, s1);
            float bw = __expf(-(s0 + s1));

            const float4 p1 = P1[ni], p2 = P2[ni];
            const float i2v = P3[ni].x;
            // Channel 0
            float d0 = ce0 - p1.x;
            float sA = cv0 + p1.y;
            bool m0 = (d0 * d0 < g2 * sA) &
                      !((cz0 | (p1.y == 0.0f)) & (d0 != 0.0f));
            // Channel 1
            float d1 = ce1 - p1.z;
            float sB = cv1 + p1.w;
            bool m1 = (d1 * d1 < g2 * sB) &
                      !((cz1 | (p1.w == 0.0f)) & (d1 != 0.0f));
            // Channel 2
            float d2c = ce2 - p2.x;
            float sC = cv2 + p2.y;
            bool m2 = (d2c * d2c < g2 * sC) &
                      !((cz2 | (p2.y == 0.0f)) & (d2c != 0.0f));

            bool mem = m0 & m1 & m2;
            if (dx == RADIUS) mem = mem | (dy == RADIUS);  // center forced in
            float fw = mem ? bw : 0.0f;
            sumw += fw;
            ac0 = fmaf(p2.z, fw, ac0);
            ac1 = fmaf(p2.w, fw, ac1);
            ac2 = fmaf(i2v, fw, ac2);
        }
    }

    float inv = __fdiv_rn(1.0f, fmaxf(sumw, 1e-10f));
    const int ox = blockIdx.x * BX + tx;
    const int oy = blockIdx.y * BY + ty;
    const int o = oy * IMG_W + ox;
    out[o] = ac0 * inv;
    out[HW + o] = ac1 * inv;
    out[2 * HW + o] = ac2 * inv;
}

extern "C" void kernel_launch(void* const* d_in, const int* in_sizes, int n_in,
                              void* d_out, int out_size) {
    const float* img = (const float*)d_in[0];
    const float* gd  = (const float*)d_in[1];
    const float* est = (const float*)d_in[2];
    const float* var = (const float*)d_in[3];
    const int*   spp = (const int*)d_in[4];
    float* out = (float*)d_out;

    dim3 block(BX, BY);
    dim3 grid(IMG_W / BX, IMG_H / BY);
    denoise_kernel<<<grid, block, SMEM_BYTES>>>(img, gd, est, var, spp, out);
}

// round 4
// speedup vs baseline: 6.0111x; 1.3324x over previous
#include <cuda_runtime.h>
#include <cstdint>

#define RADIUS 5
#define KS 11
#define IMG_H 256
#define IMG_W 256
#define HW (IMG_H * IMG_W)
#define BX 32
#define BYT 4            // thread y-dim; each thread owns output rows 2ty, 2ty+1
#define OUTY 8           // output rows per block
#define TX 42            // halo tile width
#define TYR 18           // halo tile height (8 + 2*5)
#define PLANE (TYR * TX) // 756
// smem: G0(16B) G1(16B) P1(16B) P2(16B) P3(4B) per pixel = 68 B/px
#define SMEM_BYTES (PLANE * 68)

// ---------------------------------------------------------------------------
// packed f32x2 helpers (Blackwell FFMA2/FADD2 path)
// ---------------------------------------------------------------------------
__device__ __forceinline__ uint64_t pk2(float lo, float hi) {
    uint64_t r; asm("mov.b64 %0, {%1,%2};" : "=l"(r) : "f"(lo), "f"(hi)); return r;
}
__device__ __forceinline__ void unpk2(float& lo, float& hi, uint64_t v) {
    asm("mov.b64 {%0,%1}, %2;" : "=f"(lo), "=f"(hi) : "l"(v));
}
__device__ __forceinline__ uint64_t add2(uint64_t a, uint64_t b) {
    uint64_t d; asm("add.rn.f32x2 %0,%1,%2;" : "=l"(d) : "l"(a), "l"(b)); return d;
}
__device__ __forceinline__ uint64_t mul2(uint64_t a, uint64_t b) {
    uint64_t d; asm("mul.rn.f32x2 %0,%1,%2;" : "=l"(d) : "l"(a), "l"(b)); return d;
}
__device__ __forceinline__ uint64_t fma2(uint64_t a, uint64_t b, uint64_t c) {
    uint64_t d; asm("fma.rn.f32x2 %0,%1,%2,%3;" : "=l"(d) : "l"(a), "l"(b), "l"(c)); return d;
}

// ---------------------------------------------------------------------------
// f32 ndtri replicating jax.scipy.special.ndtri (cephes, no FMA contraction).
// ---------------------------------------------------------------------------
template <int N>
__device__ __forceinline__ float polevl_f(float x, const float (&c)[N]) {
    float r = c[0];
#pragma unroll
    for (int i = 1; i < N; ++i) r = __fadd_rn(__fmul_rn(r, x), c[i]);
    return r;
}

__device__ float ndtri_f32(float p) {
    const float P0[5] = {-5.99633501014107895267e1f, 9.80010754185999661536e1f,
                         -5.66762857469070293439e1f, 1.39312609387279679503e1f,
                         -1.23916583867381258016e0f};
    const float Q0[9] = {1.0f, 1.95448858338141759834e0f, 4.67627912898881538453e0f,
                         8.63602421390890590575e1f, -2.25462687854119370527e2f,
                         2.00260212380060660359e2f, -8.20372256168538034246e1f,
                         1.59056225126211695515e1f, -1.18331621121330003142e0f};
    const float P1c[9] = {4.05544892305962419923e0f, 3.15251094599893866154e1f,
                          5.71628192246421288162e1f, 4.40805073893200834700e1f,
                          1.46849561928858024014e1f, 2.18663306850790267539e0f,
                          -1.40256079171354495875e-1f, -3.50424626827848203418e-2f,
                          -8.57456785154685413611e-4f};
    const float Q1c[9] = {1.0f, 1.57799883256466749731e1f, 4.53907635128879210584e1f,
                          4.13172038254672030440e1f, 1.50425385692907503408e1f,
                          2.50464946208309415979e0f, -1.42182922854787788574e-1f,
                          -3.80806407691578277194e-2f, -9.33259480895457427372e-4f};
    const float P2c[9] = {3.23774891776946035970e0f, 6.91522889068984211695e0f,
                          3.93881025292474443415e0f, 1.33303460815807542389e0f,
                          2.01485389549179081538e-1f, 1.23716634817820021358e-2f,
                          3.01581553508235416007e-4f, 2.65806974686737550832e-6f,
                          6.23974539184983651783e-9f};
    const float Q2c[9] = {1.0f, 6.02427039364742014255e0f, 3.67983563856160859403e0f,
                          1.37702099489081330271e0f, 2.16236993594496635890e-1f,
                          1.34204006088543189037e-2f, 3.28014464682127739104e-4f,
                          2.89247864745380683936e-6f, 6.79019408009981274425e-9f};
    const float one_m_expm2 = 0.86466471676338730811f;
    const float expm2 = 0.13533528323661269189f;

    float mcp = (p > one_m_expm2) ? __fadd_rn(1.0f, -p) : p;
    float san = (mcp <= 0.0f) ? 0.5f : mcp;
    float x;
    if (san > expm2) {
        float w = __fadd_rn(san, -0.5f);
        float ww = __fmul_rn(w, w);
        float r = __fdiv_rn(polevl_f(ww, P0), polevl_f(ww, Q0));
        x = __fadd_rn(w, __fmul_rn(__fmul_rn(w, ww), r));
        x = __fmul_rn(x, -2.50662827463100050242f);
    } else {
        float z = __fsqrt_rn(__fmul_rn(-2.0f, logf(san)));
        float ft = __fadd_rn(z, -__fdiv_rn(logf(z), z));
        float iz = __fdiv_rn(1.0f, z);
        float num, den;
        if (z >= 8.0f) { num = polevl_f(iz, P2c); den = polevl_f(iz, Q2c); }
        else           { num = polevl_f(iz, P1c); den = polevl_f(iz, Q1c); }
        float st = __fdiv_rn(__fdiv_rn(num, den), z);
        x = __fadd_rn(ft, -st);
    }
    return (p > one_m_expm2) ? x : -x;
}

__device__ float compute_gamma(int spp) {
    float z = ndtri_f32(0.9975f);
    double df = (double)(2 * spp - 2);
    float z2 = __fmul_rn(z, z);
    float z3 = __fmul_rn(z, z2);
    float z4 = __fmul_rn(z2, z2);
    float z5 = __fmul_rn(z, z4);
    float z7 = __fmul_rn(z3, z4);
    float g1 = __fdiv_rn(__fadd_rn(z3, z), (float)(4.0 * df));
    float g2 = __fdiv_rn(
        __fadd_rn(__fadd_rn(__fmul_rn(5.0f, z5), __fmul_rn(16.0f, z3)), __fmul_rn(3.0f, z)),
        (float)(96.0 * df * df));
    float g3 = __fdiv_rn(
        __fadd_rn(__fadd_rn(__fadd_rn(__fmul_rn(3.0f, z7), __fmul_rn(19.0f, z5)),
                            __fmul_rn(17.0f, z3)),
                  -__fmul_rn(15.0f, z)),
        (float)(384.0 * df * df * df));
    return __fadd_rn(__fadd_rn(__fadd_rn(z, g1), g2), g3);
}

// ---------------------------------------------------------------------------
// Denoiser: block (32,4,2) = 256 thr; each (tx,ty) pair of threads produces
// output rows 2ty and 2ty+1 (tz splits the 12-row neighbor span, 6 rows each).
// Guidance staged pre-scaled by sqrt(0.5*sigma*log2e); variance zero-poisoned.
// ---------------------------------------------------------------------------
__global__ void __launch_bounds__(256)
denoise_kernel(const float* __restrict__ img, const float* __restrict__ gd,
               const float* __restrict__ est, const float* __restrict__ var,
               const int* __restrict__ spp_p, float* __restrict__ out) {
    extern __shared__ char smraw[];
    float4* G0 = (float4*)smraw;
    float4* G1 = (float4*)(smraw + 16 * PLANE);
    float4* P1 = (float4*)(smraw + 32 * PLANE);
    float4* P2 = (float4*)(smraw + 48 * PLANE);
    float*  P3 = (float*) (smraw + 64 * PLANE);
    __shared__ float s_g2;

    const int tx = threadIdx.x, ty = threadIdx.y, tz = threadIdx.z;
    const int tid = (tz * BYT + ty) * BX + tx;
    const int gx0 = blockIdx.x * BX - RADIUS;
    const int gy0 = blockIdx.y * OUTY - RADIUS;
    const float NINF = __int_as_float(0xff800000);
    // sqrt(0.5 * sigma_c * log2(e))
    const float SCA = 0.26857906f;   // sigma 0.1
    const float SCB = 6.00561167f;   // sigma 50
    const float SCC = 2.68579063f;   // sigma 10

    for (int i = tid; i < PLANE; i += 256) {
        int ly = i / TX, lx = i - ly * TX;
        int gy = gy0 + ly, gx = gx0 + lx;
        bool inb = ((unsigned)gy < IMG_H) & ((unsigned)gx < IMG_W);
        int g = gy * IMG_W + gx;
        float4 a, b, p1, p2; float p3;
        if (inb) {
            a = make_float4(gd[g] * SCA, gd[HW + g] * SCA,
                            gd[2 * HW + g] * SCB, gd[3 * HW + g] * SCB);
            b = make_float4(gd[4 * HW + g] * SCB, gd[5 * HW + g] * SCC,
                            gd[6 * HW + g] * SCC, gd[7 * HW + g] * SCC);
            float v0 = var[g], v1 = var[HW + g], v2 = var[2 * HW + g];
            v0 = (v0 == 0.f) ? NINF : v0;
            v1 = (v1 == 0.f) ? NINF : v1;
            v2 = (v2 == 0.f) ? NINF : v2;
            p1 = make_float4(est[g], v0, est[HW + g], v1);
            p2 = make_float4(est[2 * HW + g], v2, img[g], img[HW + g]);
            p3 = img[2 * HW + g];
        } else {
            a = make_float4(0.f, 0.f, 0.f, 0.f); b = a;
            p1 = make_float4(0.f, NINF, 0.f, NINF);
            p2 = make_float4(0.f, NINF, 0.f, 0.f);
            p3 = 0.f;
        }
        G0[i] = a; G1[i] = b; P1[i] = p1; P2[i] = p2; P3[i] = p3;
    }
    if (tid == 0) { float gm = compute_gamma(spp_p[0]); s_g2 = gm * gm; }
    __syncthreads();
    const float g2 = s_g2;
    const unsigned sbase = (unsigned)__cvta_generic_to_shared(smraw);

    // Center data for both owned pixels.
    const int ci0 = (2 * ty + RADIUS) * TX + tx + RADIUS;
    const int ci1 = ci0 + TX;
    const float4 cga = G0[ci0], cgb = G1[ci0];
    const float4 cha = G0[ci1], chb = G1[ci1];
    const uint64_t n0a = pk2(-cga.x, -cga.y), n0b = pk2(-cga.z, -cga.w);
    const uint64_t n0c = pk2(-cgb.x, -cgb.y), n0d = pk2(-cgb.z, -cgb.w);
    const uint64_t n1a = pk2(-cha.x, -cha.y), n1b = pk2(-cha.z, -cha.w);
    const uint64_t n1c = pk2(-chb.x, -chb.y), n1d = pk2(-chb.z, -chb.w);
    const float4 q10 = P1[ci0], q20 = P2[ci0];
    const float4 q11 = P1[ci1], q21 = P2[ci1];

    float sw0 = 0.f, a00 = 0.f, a01 = 0.f, a02 = 0.f;
    float sw1 = 0.f, a10 = 0.f, a11 = 0.f, a12 = 0.f;
    const int rstart = tz * 6;

#pragma unroll 1
    for (int rr = 0; rr < 6; ++rr) {
        const int r = rstart + rr;                  // 0..11 over the 12-row span
        const bool act0 = (r <= 10), act1 = (r >= 1);
        const int rowb = (2 * ty + r) * TX + tx;
#pragma unroll
        for (int dx = 0; dx < KS; ++dx) {
            const int ni = rowb + dx;
            const unsigned ga = sbase + (unsigned)(ni * 16);
            uint64_t g01, g23, g45, g67;
            asm("ld.shared.v2.u64 {%0,%1}, [%2];"
                : "=l"(g01), "=l"(g23) : "r"(ga));
            asm("ld.shared.v2.u64 {%0,%1}, [%2+12096];"   // +16*PLANE
                : "=l"(g45), "=l"(g67) : "r"(ga));
            // bilateral weight, center 0
            uint64_t d0a = add2(g01, n0a), d0b = add2(g23, n0b);
            uint64_t d0c = add2(g45, n0c), d0d = add2(g67, n0d);
            uint64_t sA0 = mul2(d0a, d0a), sB0 = mul2(d0b, d0b);
            sA0 = fma2(d0c, d0c, sA0); sB0 = fma2(d0d, d0d, sB0);
            sA0 = add2(sA0, sB0);
            float lo0, hi0; unpk2(lo0, hi0, sA0);
            float bw0; asm("ex2.approx.f32 %0, %1;" : "=f"(bw0) : "f"(-lo0 - hi0));
            // bilateral weight, center 1
            uint64_t d1a = add2(g01, n1a), d1b = add2(g23, n1b);
            uint64_t d1c = add2(g45, n1c), d1d = add2(g67, n1d);
            uint64_t sA1 = mul2(d1a, d1a), sB1 = mul2(d1b, d1b);
            sA1 = fma2(d1c, d1c, sA1); sB1 = fma2(d1d, d1d, sB1);
            sA1 = add2(sA1, sB1);
            float lo1, hi1; unpk2(lo1, hi1, sA1);
            float bw1; asm("ex2.approx.f32 %0, %1;" : "=f"(bw1) : "f"(-lo1 - hi1));

            const float4 p1 = P1[ni];
            const float4 p2 = P2[ni];
            const float i2 = P3[ni];
            // membership, center 0 (mem <=> d^2 < g2*(cv+sv); -inf poison excludes)
            float d, s, dd2;
            d = q10.x - p1.x; s = q10.y + p1.y; dd2 = d * d;
            bool m00 = fmaf(g2, s, -dd2) > 0.f;
            d = q10.z - p1.z; s = q10.w + p1.w; dd2 = d * d;
            bool m01 = fmaf(g2, s, -dd2) > 0.f;
            d = q20.x - p2.x; s = q20.y + p2.y; dd2 = d * d;
            bool m02 = fmaf(g2, s, -dd2) > 0.f;
            bool mem0 = m00 & m01 & m02;
            // membership, center 1
            d = q11.x - p1.x; s = q11.y + p1.y; dd2 = d * d;
            bool m10 = fmaf(g2, s, -dd2) > 0.f;
            d = q11.z - p1.z; s = q11.w + p1.w; dd2 = d * d;
            bool m11 = fmaf(g2, s, -dd2) > 0.f;
            d = q21.x - p2.x; s = q21.y + p2.y; dd2 = d * d;
            bool m12 = fmaf(g2, s, -dd2) > 0.f;
            bool mem1 = m10 & m11 & m12;

            if (dx == RADIUS) {                      // force own center pixel in
                mem0 = mem0 | (r == RADIUS);
                mem1 = mem1 | (r == RADIUS + 1);
            }
            mem0 = mem0 & act0;
            mem1 = mem1 & act1;
            float fw0 = mem0 ? bw0 : 0.f;
            float fw1 = mem1 ? bw1 : 0.f;
            sw0 += fw0;
            a00 = fmaf(p2.z, fw0, a00); a01 = fmaf(p2.w, fw0, a01); a02 = fmaf(i2, fw0, a02);
            sw1 += fw1;
            a10 = fmaf(p2.z, fw1, a10); a11 = fmaf(p2.w, fw1, a11); a12 = fmaf(i2, fw1, a12);
        }
    }

    // Combine tz-partials through smem (reuse staging region).
    __syncthreads();
    float4* R = (float4*)smraw;
    const int o0 = (2 * ty) * BX + tx;
    R[o0 + 256 * tz] = make_float4(sw0, a00, a01, a02);
    R[o0 + BX + 256 * tz] = make_float4(sw1, a10, a11, a12);
    __syncthreads();
    {
        float4 u = R[tid], v = R[tid + 256];
        float swt = u.x + v.x;
        float inv = __fdiv_rn(1.0f, fmaxf(swt, 1e-10f));
        int ox = blockIdx.x * BX + (tid & 31);
        int oy = blockIdx.y * OUTY + (tid >> 5);
        int o = oy * IMG_W + ox;
        out[o] = (u.y + v.y) * inv;
        out[HW + o] = (u.z + v.z) * inv;
        out[2 * HW + o] = (u.w + v.w) * inv;
    }
}

extern "C" void kernel_launch(void* const* d_in, const int* in_sizes, int n_in,
                              void* d_out, int out_size) {
    const float* img = (const float*)d_in[0];
    const float* gd  = (const float*)d_in[1];
    const float* est = (const float*)d_in[2];
    const float* var = (const float*)d_in[3];
    const int*   spp = (const int*)d_in[4];
    float* out = (float*)d_out;

    static bool attr_set = false;
    if (!attr_set) {
        cudaFuncSetAttribute(denoise_kernel,
                             cudaFuncAttributeMaxDynamicSharedMemorySize, SMEM_BYTES);
        attr_set = true;
    }
    dim3 block(BX, BYT, 2);
    dim3 grid(IMG_W / BX, IMG_H / OUTY);
    denoise_kernel<<<grid, block, SMEM_BYTES>>>(img, gd, est, var, spp, out);
}

// round 5
// speedup vs baseline: 6.0955x; 1.0140x over previous
#include <cuda_runtime.h>
#include <cstdint>

#define RADIUS 5
#define KS 11
#define IMG_H 256
#define IMG_W 256
#define HW (IMG_H * IMG_W)
#define BX 32
#define BYT 2            // ty dim; each thread owns output rows 2ty, 2ty+1
#define TZ 4             // window split: 3 rows per tz
#define OUTY 4           // output rows per block
#define TX 42            // halo width
#define TYR 14           // halo height (4 + 10)
#define PLANE (TYR * TX) // 588
// per-pixel smem: G0(16) G1(16) P1(16) P2(16) P3(4) = 68 B
#define SMEM_BYTES (PLANE * 68)
#define OFF_G1 (16 * PLANE)
#define OFF_P1 (32 * PLANE)
#define OFF_P2 (48 * PLANE)
#define OFF_P3 (64 * PLANE)

// ---------------------------------------------------------------------------
// packed f32x2 helpers
// ---------------------------------------------------------------------------
__device__ __forceinline__ uint64_t pk2(float lo, float hi) {
    uint64_t r; asm("mov.b64 %0, {%1,%2};" : "=l"(r) : "f"(lo), "f"(hi)); return r;
}
__device__ __forceinline__ void unpk2(float& lo, float& hi, uint64_t v) {
    asm("mov.b64 {%0,%1}, %2;" : "=f"(lo), "=f"(hi) : "l"(v));
}
__device__ __forceinline__ uint64_t add2(uint64_t a, uint64_t b) {
    uint64_t d; asm("add.rn.f32x2 %0,%1,%2;" : "=l"(d) : "l"(a), "l"(b)); return d;
}
__device__ __forceinline__ uint64_t mul2(uint64_t a, uint64_t b) {
    uint64_t d; asm("mul.rn.f32x2 %0,%1,%2;" : "=l"(d) : "l"(a), "l"(b)); return d;
}
__device__ __forceinline__ uint64_t fma2(uint64_t a, uint64_t b, uint64_t c) {
    uint64_t d; asm("fma.rn.f32x2 %0,%1,%2,%3;" : "=l"(d) : "l"(a), "l"(b), "l"(c)); return d;
}

// ---------------------------------------------------------------------------
// f32 ndtri replicating jax.scipy.special.ndtri (cephes, no FMA contraction).
// ---------------------------------------------------------------------------
template <int N>
__device__ __forceinline__ float polevl_f(float x, const float (&c)[N]) {
    float r = c[0];
#pragma unroll
    for (int i = 1; i < N; ++i) r = __fadd_rn(__fmul_rn(r, x), c[i]);
    return r;
}

__device__ float ndtri_f32(float p) {
    const float P0[5] = {-5.99633501014107895267e1f, 9.80010754185999661536e1f,
                         -5.66762857469070293439e1f, 1.39312609387279679503e1f,
                         -1.23916583867381258016e0f};
    const float Q0[9] = {1.0f, 1.95448858338141759834e0f, 4.67627912898881538453e0f,
                         8.63602421390890590575e1f, -2.25462687854119370527e2f,
                         2.00260212380060660359e2f, -8.20372256168538034246e1f,
                         1.59056225126211695515e1f, -1.18331621121330003142e0f};
    const float P1c[9] = {4.05544892305962419923e0f, 3.15251094599893866154e1f,
                          5.71628192246421288162e1f, 4.40805073893200834700e1f,
                          1.46849561928858024014e1f, 2.18663306850790267539e0f,
                          -1.40256079171354495875e-1f, -3.50424626827848203418e-2f,
                          -8.57456785154685413611e-4f};
    const float Q1c[9] = {1.0f, 1.57799883256466749731e1f, 4.53907635128879210584e1f,
                          4.13172038254672030440e1f, 1.50425385692907503408e1f,
                          2.50464946208309415979e0f, -1.42182922854787788574e-1f,
                          -3.80806407691578277194e-2f, -9.33259480895457427372e-4f};
    const float P2c[9] = {3.23774891776946035970e0f, 6.91522889068984211695e0f,
                          3.93881025292474443415e0f, 1.33303460815807542389e0f,
                          2.01485389549179081538e-1f, 1.23716634817820021358e-2f,
                          3.01581553508235416007e-4f, 2.65806974686737550832e-6f,
                          6.23974539184983651783e-9f};
    const float Q2c[9] = {1.0f, 6.02427039364742014255e0f, 3.67983563856160859403e0f,
                          1.37702099489081330271e0f, 2.16236993594496635890e-1f,
                          1.34204006088543189037e-2f, 3.28014464682127739104e-4f,
                          2.89247864745380683936e-6f, 6.79019408009981274425e-9f};
    const float one_m_expm2 = 0.86466471676338730811f;
    const float expm2 = 0.13533528323661269189f;

    float mcp = (p > one_m_expm2) ? __fadd_rn(1.0f, -p) : p;
    float san = (mcp <= 0.0f) ? 0.5f : mcp;
    float x;
    if (san > expm2) {
        float w = __fadd_rn(san, -0.5f);
        float ww = __fmul_rn(w, w);
        float r = __fdiv_rn(polevl_f(ww, P0), polevl_f(ww, Q0));
        x = __fadd_rn(w, __fmul_rn(__fmul_rn(w, ww), r));
        x = __fmul_rn(x, -2.50662827463100050242f);
    } else {
        float z = __fsqrt_rn(__fmul_rn(-2.0f, logf(san)));
        float ft = __fadd_rn(z, -__fdiv_rn(logf(z), z));
        float iz = __fdiv_rn(1.0f, z);
        float num, den;
        if (z >= 8.0f) { num = polevl_f(iz, P2c); den = polevl_f(iz, Q2c); }
        else           { num = polevl_f(iz, P1c); den = polevl_f(iz, Q1c); }
        float st = __fdiv_rn(__fdiv_rn(num, den), z);
        x = __fadd_rn(ft, -st);
    }
    return (p > one_m_expm2) ? x : -x;
}

__device__ float compute_gamma(int spp) {
    float z = ndtri_f32(0.9975f);
    double df = (double)(2 * spp - 2);
    float z2 = __fmul_rn(z, z);
    float z3 = __fmul_rn(z, z2);
    float z4 = __fmul_rn(z2, z2);
    float z5 = __fmul_rn(z, z4);
    float z7 = __fmul_rn(z3, z4);
    float g1 = __fdiv_rn(__fadd_rn(z3, z), (float)(4.0 * df));
    float g2 = __fdiv_rn(
        __fadd_rn(__fadd_rn(__fmul_rn(5.0f, z5), __fmul_rn(16.0f, z3)), __fmul_rn(3.0f, z)),
        (float)(96.0 * df * df));
    float g3 = __fdiv_rn(
        __fadd_rn(__fadd_rn(__fadd_rn(__fmul_rn(3.0f, z7), __fmul_rn(19.0f, z5)),
                            __fmul_rn(17.0f, z3)),
                  -__fmul_rn(15.0f, z)),
        (float)(384.0 * df * df * df));
    return __fadd_rn(__fadd_rn(__fadd_rn(z, g1), g2), g3);
}

// ---------------------------------------------------------------------------
// Denoiser: block (32,2,4)=256 thr, 512 blocks. Each (tx,ty) owns output rows
// 2ty,2ty+1; tz splits the 12-row neighbor span into 3-row chunks (4-way).
// ---------------------------------------------------------------------------
__global__ void __launch_bounds__(256, 4)
denoise_kernel(const float* __restrict__ img, const float* __restrict__ gd,
               const float* __restrict__ est, const float* __restrict__ var,
               const int* __restrict__ spp_p, float* __restrict__ out) {
    extern __shared__ char smraw[];
    float4* G0 = (float4*)smraw;
    float4* G1 = (float4*)(smraw + OFF_G1);
    float4* P1 = (float4*)(smraw + OFF_P1);
    float4* P2 = (float4*)(smraw + OFF_P2);
    float*  P3 = (float*) (smraw + OFF_P3);
    __shared__ float s_g2;

    const int tx = threadIdx.x, ty = threadIdx.y, tz = threadIdx.z;
    const int tid = (tz * BYT + ty) * BX + tx;
    const int gx0 = blockIdx.x * BX - RADIUS;
    const int gy0 = blockIdx.y * OUTY - RADIUS;
    const float NINF = __int_as_float(0xff800000);
    // sqrt(0.5 * sigma_c * log2(e))
    const float SCA = 0.26857906f;   // sigma 0.1
    const float SCB = 6.00561167f;   // sigma 50
    const float SCC = 2.68579063f;   // sigma 10

    for (int i = tid; i < PLANE; i += 256) {
        int ly = i / TX, lx = i - ly * TX;
        int gy = gy0 + ly, gx = gx0 + lx;
        bool inb = ((unsigned)gy < IMG_H) & ((unsigned)gx < IMG_W);
        int g = gy * IMG_W + gx;
        float4 a, b, p1, p2; float p3;
        if (inb) {
            a = make_float4(gd[g] * SCA, gd[HW + g] * SCA,
                            gd[2 * HW + g] * SCB, gd[3 * HW + g] * SCB);
            b = make_float4(gd[4 * HW + g] * SCB, gd[5 * HW + g] * SCC,
                            gd[6 * HW + g] * SCC, gd[7 * HW + g] * SCC);
            float v0 = var[g], v1 = var[HW + g], v2 = var[2 * HW + g];
            v0 = (v0 == 0.f) ? NINF : v0;
            v1 = (v1 == 0.f) ? NINF : v1;
            v2 = (v2 == 0.f) ? NINF : v2;
            p1 = make_float4(est[g], v0, est[HW + g], v1);
            p2 = make_float4(est[2 * HW + g], v2, img[g], img[HW + g]);
            p3 = img[2 * HW + g];
        } else {
            a = make_float4(0.f, 0.f, 0.f, 0.f); b = a;
            p1 = make_float4(0.f, NINF, 0.f, NINF);
            p2 = make_float4(0.f, NINF, 0.f, 0.f);
            p3 = 0.f;
        }
        G0[i] = a; G1[i] = b; P1[i] = p1; P2[i] = p2; P3[i] = p3;
    }
    if (tid == 0) { float gm = compute_gamma(spp_p[0]); s_g2 = gm * gm; }
    __syncthreads();
    const float g2 = s_g2;
    const unsigned sbase = (unsigned)__cvta_generic_to_shared(smraw);

    // Center data for both owned pixels (rows 2ty, 2ty+1).
    const int ci0 = (2 * ty + RADIUS) * TX + tx + RADIUS;
    const int ci1 = ci0 + TX;
    const float4 cga = G0[ci0], cgb = G1[ci0];
    const float4 cha = G0[ci1], chb = G1[ci1];
    const uint64_t n0a = pk2(-cga.x, -cga.y), n0b = pk2(-cga.z, -cga.w);
    const uint64_t n0c = pk2(-cgb.x, -cgb.y), n0d = pk2(-cgb.z, -cgb.w);
    const uint64_t n1a = pk2(-cha.x, -cha.y), n1b = pk2(-cha.z, -cha.w);
    const uint64_t n1c = pk2(-chb.x, -chb.y), n1d = pk2(-chb.z, -chb.w);
    const float4 q10 = P1[ci0], q20 = P2[ci0];
    const float4 q11 = P1[ci1], q21 = P2[ci1];
    // center words (-ce, cv) so add2 with neighbor (se, sv) gives (-d, s)
    const uint64_t c00 = pk2(-q10.x, q10.y), c01 = pk2(-q10.z, q10.w),
                   c02 = pk2(-q20.x, q20.y);
    const uint64_t c10 = pk2(-q11.x, q11.y), c11 = pk2(-q11.z, q11.w),
                   c12 = pk2(-q21.x, q21.y);

    float sw0 = 0.f, a00 = 0.f, a01 = 0.f, a02 = 0.f;
    float sw1 = 0.f, a10 = 0.f, a11 = 0.f, a12 = 0.f;
    const int rstart = tz * 3;

#pragma unroll
    for (int rr = 0; rr < 3; ++rr) {
        const int r = rstart + rr;                  // 0..11 over the 12-row span
        const bool act0 = (r <= 10), act1 = (r >= 1);
        const bool f0 = (r == RADIUS), f1 = (r == RADIUS + 1);
        const int rowb = (2 * ty + r) * TX + tx;
        const unsigned ga = sbase + (unsigned)(rowb * 16);
        const unsigned pa = sbase + (unsigned)(OFF_P3 + rowb * 4);
#pragma unroll
        for (int dx = 0; dx < KS; ++dx) {
            uint64_t g01, g23, g45, g67, p1lo, p1hi, p2lo, p2hi;
            float i2;
            asm("ld.shared.v2.u64 {%0,%1}, [%2];"
                : "=l"(g01), "=l"(g23) : "r"(ga + dx * 16));
            asm("ld.shared.v2.u64 {%0,%1}, [%2];"
                : "=l"(g45), "=l"(g67) : "r"(ga + dx * 16 + OFF_G1));
            asm("ld.shared.v2.u64 {%0,%1}, [%2];"
                : "=l"(p1lo), "=l"(p1hi) : "r"(ga + dx * 16 + OFF_P1));
            asm("ld.shared.v2.u64 {%0,%1}, [%2];"
                : "=l"(p2lo), "=l"(p2hi) : "r"(ga + dx * 16 + OFF_P2));
            asm("ld.shared.f32 %0, [%1];" : "=f"(i2) : "r"(pa + dx * 4));

            // bilateral weight, center 0
            uint64_t d0a = add2(g01, n0a), d0b = add2(g23, n0b);
            uint64_t d0c = add2(g45, n0c), d0d = add2(g67, n0d);
            uint64_t sA0 = mul2(d0a, d0a), sB0 = mul2(d0b, d0b);
            sA0 = fma2(d0c, d0c, sA0); sB0 = fma2(d0d, d0d, sB0);
            sA0 = add2(sA0, sB0);
            float lo0, hi0; unpk2(lo0, hi0, sA0);
            float bw0; asm("ex2.approx.f32 %0, %1;" : "=f"(bw0) : "f"(-lo0 - hi0));
            // bilateral weight, center 1
            uint64_t d1a = add2(g01, n1a), d1b = add2(g23, n1b);
            uint64_t d1c = add2(g45, n1c), d1d = add2(g67, n1d);
            uint64_t sA1 = mul2(d1a, d1a), sB1 = mul2(d1b, d1b);
            sA1 = fma2(d1c, d1c, sA1); sB1 = fma2(d1d, d1d, sB1);
            sA1 = add2(sA1, sB1);
            float lo1, hi1; unpk2(lo1, hi1, sA1);
            float bw1; asm("ex2.approx.f32 %0, %1;" : "=f"(bw1) : "f"(-lo1 - hi1));

            // membership: per channel, packed (se,sv)+( -ce,cv ) -> (-d, s)
            float md, s;
            uint64_t t;
            t = add2(p1lo, c00); unpk2(md, s, t);
            bool m00 = fmaf(g2, s, -(md * md)) > 0.f;
            t = add2(p1hi, c01); unpk2(md, s, t);
            bool m01 = fmaf(g2, s, -(md * md)) > 0.f;
            t = add2(p2lo, c02); unpk2(md, s, t);
            bool m02 = fmaf(g2, s, -(md * md)) > 0.f;
            bool mem0 = m00 & m01 & m02;
            t = add2(p1lo, c10); unpk2(md, s, t);
            bool m10 = fmaf(g2, s, -(md * md)) > 0.f;
            t = add2(p1hi, c11); unpk2(md, s, t);
            bool m11 = fmaf(g2, s, -(md * md)) > 0.f;
            t = add2(p2lo, c12); unpk2(md, s, t);
            bool m12 = fmaf(g2, s, -(md * md)) > 0.f;
            bool mem1 = m10 & m11 & m12;

            if (dx == RADIUS) {                      // force own center pixel in
                mem0 = mem0 | f0;
                mem1 = mem1 | f1;
            }
            mem0 = mem0 & act0;
            mem1 = mem1 & act1;
            float fw0 = mem0 ? bw0 : 0.f;
            float fw1 = mem1 ? bw1 : 0.f;
            float iv0, iv1;
            unpk2(iv0, iv1, p2hi);                   // (i0, i1)
            sw0 += fw0;
            a00 = fmaf(iv0, fw0, a00); a01 = fmaf(iv1, fw0, a01); a02 = fmaf(i2, fw0, a02);
            sw1 += fw1;
            a10 = fmaf(iv0, fw1, a10); a11 = fmaf(iv1, fw1, a11); a12 = fmaf(i2, fw1, a12);
        }
    }

    // 4-way tz reduction through smem (conflict-free layout R[tz*128 + pix]).
    __syncthreads();
    float4* R = (float4*)smraw;
    const int pix0 = (2 * ty) * BX + tx;
    R[tz * 128 + pix0] = make_float4(sw0, a00, a01, a02);
    R[tz * 128 + pix0 + BX] = make_float4(sw1, a10, a11, a12);
    __syncthreads();
    if (tid < 128) {
        float4 u = R[tid], v = R[128 + tid], w = R[256 + tid], x = R[384 + tid];
        float swt = (u.x + v.x) + (w.x + x.x);
        float inv = __fdiv_rn(1.0f, fmaxf(swt, 1e-10f));
        int ox = blockIdx.x * BX + (tid & 31);
        int oy = blockIdx.y * OUTY + (tid >> 5);
        int o = oy * IMG_W + ox;
        out[o] = ((u.y + v.y) + (w.y + x.y)) * inv;
        out[HW + o] = ((u.z + v.z) + (w.z + x.z)) * inv;
        out[2 * HW + o] = ((u.w + v.w) + (w.w + x.w)) * inv;
    }
}

extern "C" void kernel_launch(void* const* d_in, const int* in_sizes, int n_in,
                              void* d_out, int out_size) {
    const float* img = (const float*)d_in[0];
    const float* gd  = (const float*)d_in[1];
    const float* est = (const float*)d_in[2];
    const float* var = (const float*)d_in[3];
    const int*   spp = (const int*)d_in[4];
    float* out = (float*)d_out;

    static bool attr_set = false;
    if (!attr_set) {
        cudaFuncSetAttribute(denoise_kernel,
                             cudaFuncAttributeMaxDynamicSharedMemorySize, SMEM_BYTES);
        attr_set = true;
    }
    dim3 block(BX, BYT, TZ);
    dim3 grid(IMG_W / BX, IMG_H / OUTY);
    denoise_kernel<<<grid, block, SMEM_BYTES>>>(img, gd, est, var, spp, out);
}